// round 7
// baseline (speedup 1.0000x reference)
#include <cuda_runtime.h>
#include <math.h>

__device__ __forceinline__ float warp_sum(float v) {
#pragma unroll
    for (int o = 16; o; o >>= 1) v += __shfl_xor_sync(0xffffffffu, v, o);
    return v;
}

// One block (128 threads / 4 warps) per row i. Fully fused, 5 syncs:
//   A: row scalars (warp0, registers) + adj scan/compaction (all warps)
//   B: 4-threads-per-pair hyperbolic math, UNIFORM trip count (shuffle-safe)
//   C: dim-parallel weighted gather (parity split)
//   D: S1 + u assembly + expmap + proj epilogue (warp 0)
__global__ __launch_bounds__(128, 12)
void fused_kernel(const float* __restrict__ x,
                  const float* __restrict__ adj,
                  const float* __restrict__ att_w,
                  const float* __restrict__ att_b,
                  float* __restrict__ out, int N) {
    __shared__ float s_xi[64];
    __shared__ float s_wr[64];
    __shared__ float s_x2, s_li;
    __shared__ int   s_wcnt[4];
    __shared__ int   s_woff[4];
    __shared__ int   s_tmp[4 * 64];
    __shared__ int   s_list[128];
    __shared__ float s_g[128];
    __shared__ float s_h[128];
    __shared__ float s_acc0[64];
    __shared__ float s_acc1[64];
    __shared__ int   s_cnt;

    int row  = blockIdx.x;
    int tid  = threadIdx.x;
    int w    = tid >> 5;
    int lane = tid & 31;

    // ---- phase A: staging + row scalars + adj scan ----
    if (w == 0) {
        float x0 = x[row * 64 + lane];
        float x1 = x[row * 64 + 32 + lane];
        s_xi[lane]      = x0;
        s_xi[lane + 32] = x1;
        float n2 = warp_sum(x0 * x0 + x1 * x1);
        float dl = warp_sum(x0 * att_w[lane] + x1 * att_w[32 + lane]);
        if (lane == 0) {
            s_x2 = n2;
            float pn  = sqrtf(n2);
            float pnc = fmaxf(pn, 1e-15f);
            s_li = atanhf(fminf(pnc, 1.f - 1e-7f)) / pnc * dl;
        }
    } else if (w == 1) {
        s_wr[lane]      = att_w[64 + lane];
        s_wr[lane + 32] = att_w[96 + lane];
    }

    // adj-row scan: warp w covers float4s [w*qpw, (w+1)*qpw)
    const float4* arow = (const float4*)(adj + (size_t)row * N);
    int nq  = N >> 2;
    int qpw = (nq + 3) >> 2;
    int qb  = w * qpw;
    float4 v[3];
#pragma unroll
    for (int c = 0; c < 3; c++) {
        int qi = qb + c * 32 + lane;
        v[c] = (c * 32 + lane < qpw && qi < nq) ? __ldg(&arow[qi])
                                                : make_float4(0.f, 0.f, 0.f, 0.f);
    }
    int cw = 0;
#pragma unroll
    for (int c = 0; c < 3; c++) {
        float vals[4] = {v[c].x, v[c].y, v[c].z, v[c].w};
#pragma unroll
        for (int e = 0; e < 4; e++) {
            unsigned m = __ballot_sync(0xffffffffu, vals[e] != 0.f);
            if (vals[e] != 0.f) {
                int slot = cw + __popc(m & ((1u << lane) - 1u));
                if (slot < 64) s_tmp[w * 64 + slot] = (qb + c * 32 + lane) * 4 + e;
            }
            cw += __popc(m);
        }
    }
    if (lane == 0) s_wcnt[w] = min(cw, 64);
    __syncthreads();                                   // sync 1

    if (tid == 0) {
        int o = 0;
#pragma unroll
        for (int i = 0; i < 4; i++) { s_woff[i] = o; o += s_wcnt[i]; }
        s_cnt = min(o, 128);
    }
    __syncthreads();                                   // sync 2
    {
        int o = s_woff[w], n = s_wcnt[w];
        for (int s = lane; s < n; s += 32)
            if (o + s < 128) s_list[o + s] = s_tmp[w * 64 + s];
    }
    __syncthreads();                                   // sync 3

    int   cnt  = s_cnt;
    float x2   = s_x2;
    float li   = s_li;
    float beta = 1.f - x2;
    float bias = att_b[0];

    // ---- phase B: 4 threads per pair, 32 groups, UNIFORM rounds ----
    {
        int gr = tid >> 2;            // group 0..31
        int gl = tid & 3;             // lane in group
        int rounds = (cnt + 31) >> 5; // block-uniform
        for (int r = 0; r < rounds; r++) {
            int s = r * 32 + gr;
            bool act = (s < cnt);
            int j = act ? s_list[s] : row;     // safe dummy index when idle
            const float4* xj = (const float4*)(x + j * 64) + gl * 4;
            float D = 0.f, y2 = 0.f, rd = 0.f;
#pragma unroll
            for (int k = 0; k < 4; k++) {
                float4 q = __ldg(&xj[k]);
                int d0 = gl * 16 + k * 4;
                D  = fmaf(q.x, s_xi[d0],   fmaf(q.y, s_xi[d0+1],
                     fmaf(q.z, s_xi[d0+2], fmaf(q.w, s_xi[d0+3], D))));
                y2 = fmaf(q.x, q.x, fmaf(q.y, q.y,
                     fmaf(q.z, q.z, fmaf(q.w, q.w, y2))));
                rd = fmaf(q.x, s_wr[d0],   fmaf(q.y, s_wr[d0+1],
                     fmaf(q.z, s_wr[d0+2], fmaf(q.w, s_wr[d0+3], rd))));
            }
            // 4-lane group reduce (all 32 lanes of every warp participate)
            D  += __shfl_xor_sync(0xffffffffu, D, 1);
            y2 += __shfl_xor_sync(0xffffffffu, y2, 1);
            rd += __shfl_xor_sync(0xffffffffu, rd, 1);
            D  += __shfl_xor_sync(0xffffffffu, D, 2);
            y2 += __shfl_xor_sync(0xffffffffu, y2, 2);
            rd += __shfl_xor_sync(0xffffffffu, rd, 2);
            if (act && gl == 0) {
                float pnj  = sqrtf(y2);
                float pnjc = fmaxf(pnj, 1e-15f);
                float rv   = atanhf(fminf(pnjc, 1.f - 1e-7f)) / pnjc * rd;
                float alpha = 1.f - 2.f * D + y2;
                float den   = fmaxf(1.f - 2.f * D + x2 * y2, 1e-15f);
                float n2    = alpha * alpha * x2 - 2.f * alpha * beta * D
                            + beta * beta * y2;
                float sn    = fmaxf(sqrtf(fmaxf(n2, 0.f)) / den, 1e-15f);
                float ratio = atanhf(fminf(sn, 1.f - 1e-7f)) / sn;
                float sig   = 1.f / (1.f + expf(-(li + rv + bias)));
                float g     = sig * beta * ratio / den;
                s_g[s] = g;
                s_h[s] = g * alpha;
            }
        }
    }
    __syncthreads();                                   // sync 4

    // ---- phase C: dim-parallel gather, parity split across thread halves ----
    {
        int dd  = tid & 63;
        int par = tid >> 6;
        float acc = 0.f;
#pragma unroll 4
        for (int s = par; s < cnt; s += 2)
            acc = fmaf(s_g[s], __ldg(&x[s_list[s] * 64 + dd]), acc);
        if (par == 0) s_acc0[dd] = acc; else s_acc1[dd] = acc;
    }
    __syncthreads();                                   // sync 5

    // ---- phase D: S1 + u + expmap + proj (warp 0) ----
    if (w == 0) {
        float hv = 0.f;
#pragma unroll
        for (int b = 0; b < 4; b++) {
            int s = lane + b * 32;
            hv += (s < cnt) ? s_h[s] : 0.f;
        }
        float S1 = warp_sum(hv);

        float xi0 = s_xi[lane], xi1 = s_xi[lane + 32];
        float u0 = fmaf(beta, s_acc0[lane]      + s_acc1[lane],      -S1 * xi0);
        float u1 = fmaf(beta, s_acc0[lane + 32] + s_acc1[lane + 32], -S1 * xi1);

        float un2 = warp_sum(u0 * u0 + u1 * u1);
        float du  = warp_sum(xi0 * u0 + xi1 * u1);
        float un  = fmaxf(sqrtf(un2), 1e-15f);
        float lam = fmaxf(2.f / beta, 1e-15f);
        float t   = tanhf(0.5f * lam * un);
        float sc  = t / un;
        float s0 = sc * u0, s1 = sc * u1;
        float y2s = sc * sc * un2;
        float xys = sc * du;
        float ca   = 1.f + 2.f * xys + y2s;
        float den2 = fmaxf(1.f + 2.f * xys + x2 * y2s, 1e-15f);
        float o0 = (ca * xi0 + beta * s0) / den2;
        float o1 = (ca * xi1 + beta * s1) / den2;
        float on = fmaxf(sqrtf(warp_sum(o0 * o0 + o1 * o1)), 1e-15f);
        float maxn  = 1.f - 0.004f;
        float scale = (on > maxn) ? (maxn / on) : 1.f;
        out[row * 64 + lane]      = o0 * scale;
        out[row * 64 + 32 + lane] = o1 * scale;
    }
}

extern "C" void kernel_launch(void* const* d_in, const int* in_sizes, int n_in,
                              void* d_out, int out_size) {
    const float* x     = (const float*)d_in[0];
    const float* adj   = (const float*)d_in[1];
    const float* att_w = (const float*)d_in[2];
    const float* att_b = (const float*)d_in[3];
    int d = in_sizes[2] / 2;          // 64
    int N = in_sizes[0] / d;          // 1536
    fused_kernel<<<N, 128>>>(x, adj, att_w, att_b, (float*)d_out, N);
}